// round 1
// baseline (speedup 1.0000x reference)
#include <cuda_runtime.h>
#include <math.h>

#define NB 8
#define LQ 1024
#define HH 16
#define DD 64
#define EE 1024
#define ROWS (NB*HH*LQ)   // 131072 head-rows

// Scratch (static device globals — no allocation)
__device__ float g_q[ROWS*DD];
__device__ float g_k[ROWS*DD];
__device__ float g_v[ROWS*DD];   // v' = x @ (Wv@Wfc)
__device__ float g_Wvf[DD*DD];

// ---------------------------------------------------------------------------
// prep: Wvf = Wv @ Wfc  (64x64 @ 64x64)
// ---------------------------------------------------------------------------
__global__ void prep_kernel(const float* __restrict__ Wv,
                            const float* __restrict__ Wfc) {
    __shared__ float wv[64*64];
    __shared__ float wf[64*64];
    int tid = threadIdx.x;
    for (int i = tid; i < 4096; i += 256) { wv[i] = Wv[i]; wf[i] = Wfc[i]; }
    __syncthreads();
    for (int e = tid; e < 4096; e += 256) {
        int r = e >> 6, c = e & 63;
        float acc = 0.f;
        #pragma unroll 8
        for (int u = 0; u < 64; u++) acc += wv[r*64 + u] * wf[u*64 + c];
        g_Wvf[e] = acc;
    }
}

// ---------------------------------------------------------------------------
// projection: per (n, h, 64-row l-tile): q = x@(Wq*0.06/32), k = x@Wk, v' = x@Wvf
// smem: xs[64][65] + ws[3][64][65] + os[64][64]
// ---------------------------------------------------------------------------
__global__ __launch_bounds__(256) void proj_kernel(const float* __restrict__ x,
                                                   const float* __restrict__ Wq,
                                                   const float* __restrict__ Wk) {
    extern __shared__ float sm[];
    float* xs = sm;               // 64*65
    float* ws = xs + 64*65;       // 3 * 64*65
    float* os = ws + 3*64*65;     // 64*64
    const int tid = threadIdx.x;
    const int bid = blockIdx.x;
    const int n = bid >> 8, h = (bid >> 4) & 15, lt = bid & 15;
    const int l0 = lt << 6;
    const float qs = 0.06f / 32.0f;

    for (int idx = tid; idx < 1024; idx += 256) {
        int l = idx >> 4, t4 = (idx & 15) << 2;
        float4 v = *(const float4*)&x[(n*LQ + l0 + l)*EE + (h << 6) + t4];
        float* p = &xs[l*65 + t4];
        p[0] = v.x; p[1] = v.y; p[2] = v.z; p[3] = v.w;
    }
    for (int idx = tid; idx < 4096; idx += 256) {
        int t = idx >> 6, d = idx & 63;
        ws[t*65 + d]            = Wq[idx] * qs;
        ws[64*65 + t*65 + d]    = Wk[idx];
        ws[2*64*65 + t*65 + d]  = g_Wvf[idx];
    }
    __syncthreads();

    const int tl = tid & 15, td = tid >> 4;   // 16x16 thread grid, 4x4 tiles
    float* gouts[3] = {g_q, g_k, g_v};
    for (int w = 0; w < 3; w++) {
        const float* W = ws + w*64*65;
        float acc[4][4] = {};
        for (int t = 0; t < 64; t++) {
            float xv[4], wv[4];
            #pragma unroll
            for (int a = 0; a < 4; a++) xv[a] = xs[(tl*4 + a)*65 + t];
            #pragma unroll
            for (int b = 0; b < 4; b++) wv[b] = W[t*65 + td*4 + b];
            #pragma unroll
            for (int a = 0; a < 4; a++)
                #pragma unroll
                for (int b = 0; b < 4; b++) acc[a][b] += xv[a] * wv[b];
        }
        #pragma unroll
        for (int a = 0; a < 4; a++)
            #pragma unroll
            for (int b = 0; b < 4; b++)
                os[(tl*4 + a)*64 + td*4 + b] = acc[a][b];
        __syncthreads();
        float* gp = gouts[w] + ((n*HH + h)*LQ + l0)*DD;
        for (int idx = tid; idx < 1024; idx += 256)
            ((float4*)gp)[idx] = ((const float4*)os)[idx];
        __syncthreads();
    }
}

// ---------------------------------------------------------------------------
// attention: block = (n, h, 32-query tile). Full 32x1024 score tile in smem.
//   phase 1: S = qT * K^T  (4 chunks of 256 keys, kT[64][257] in smem)
//   phase 2: softmax rows (warp per 4 rows), write normalized attn to gmem
//   phase 3: out = P @ V'  (k-split x4, v[256][64] in smem, smem reduce)
// smem floats: 32*1025 + 64*33 + 16448 = 51360 -> 205440 B
// ---------------------------------------------------------------------------
#define SS 1025
__global__ __launch_bounds__(256) void attn_kernel(float* __restrict__ attn,
                                                   float* __restrict__ out) {
    extern __shared__ float sm[];
    float* s  = sm;               // 32*1025
    float* qT = s + 32*SS;        // 64*33
    float* kv = qT + 64*33;       // 16448 (kT 64x257 / v 256x64)
    const int tid = threadIdx.x;
    const int bid = blockIdx.x;
    const int n = bid >> 9, h = (bid >> 5) & 15, qb = bid & 31;
    const int q0 = qb << 5;
    const int base = (n*HH + h)*LQ;

    // load q tile transposed: qT[d][i], stride 33 (conflict-free)
    for (int idx = tid; idx < 512; idx += 256) {
        int i = idx >> 4, d4 = (idx & 15) << 2;
        float4 v = *(const float4*)&g_q[(base + q0 + i)*DD + d4];
        qT[(d4 + 0)*33 + i] = v.x;
        qT[(d4 + 1)*33 + i] = v.y;
        qT[(d4 + 2)*33 + i] = v.z;
        qT[(d4 + 3)*33 + i] = v.w;
    }

    const int w = tid >> 5, lane = tid & 31;
    const int ig = lane & 7, jg = lane >> 3;
    const int i0 = ig << 2;
    const int jbw = (w << 5) + (jg << 3);

    // ---- phase 1: scores ----
    for (int kb = 0; kb < 4; kb++) {
        __syncthreads();   // qT ready (kb=0) / prev compute done (kb>0)
        for (int idx = tid; idx < 4096; idx += 256) {
            int j = idx >> 4, d4 = (idx & 15) << 2;
            float4 v = *(const float4*)&g_k[(base + kb*256 + j)*DD + d4];
            kv[(d4 + 0)*257 + j] = v.x;
            kv[(d4 + 1)*257 + j] = v.y;
            kv[(d4 + 2)*257 + j] = v.z;
            kv[(d4 + 3)*257 + j] = v.w;
        }
        __syncthreads();
        float acc[4][8];
        #pragma unroll
        for (int a = 0; a < 4; a++)
            #pragma unroll
            for (int b = 0; b < 8; b++) acc[a][b] = 0.f;
        for (int d = 0; d < 64; d++) {
            float qv[4], kk[8];
            #pragma unroll
            for (int a = 0; a < 4; a++) qv[a] = qT[d*33 + i0 + a];
            #pragma unroll
            for (int b = 0; b < 8; b++) kk[b] = kv[d*257 + jbw + b];
            #pragma unroll
            for (int a = 0; a < 4; a++)
                #pragma unroll
                for (int b = 0; b < 8; b++) acc[a][b] += qv[a] * kk[b];
        }
        #pragma unroll
        for (int a = 0; a < 4; a++)
            #pragma unroll
            for (int b = 0; b < 8; b++)
                s[(i0 + a)*SS + kb*256 + jbw + b] = acc[a][b];
    }
    __syncthreads();

    // ---- phase 2: softmax (warp w handles rows 4w..4w+3) ----
    for (int rr = 0; rr < 4; rr++) {
        int row = (w << 2) + rr;
        float* srow = s + row*SS;
        float m = -1e30f;
        for (int t = lane; t < 1024; t += 32) m = fmaxf(m, srow[t]);
        #pragma unroll
        for (int off = 16; off; off >>= 1)
            m = fmaxf(m, __shfl_xor_sync(0xffffffffu, m, off));
        float sum = 0.f;
        for (int t = lane; t < 1024; t += 32) {
            float e = __expf(srow[t] - m);
            srow[t] = e;
            sum += e;
        }
        #pragma unroll
        for (int off = 16; off; off >>= 1)
            sum += __shfl_xor_sync(0xffffffffu, sum, off);
        float inv = 1.0f / sum;
        float* arow = attn + (size_t)(base + q0 + row) * 1024;
        for (int t = lane; t < 1024; t += 32) {
            float vv = srow[t] * inv;
            srow[t] = vv;
            arow[t] = vv;
        }
    }

    // ---- phase 3: out = P @ V' ----
    const int kg = tid >> 6, r = tid & 63, ig2 = r >> 3, dg = r & 7;
    const int i02 = ig2 << 2;
    float oa[4][8];
    #pragma unroll
    for (int a = 0; a < 4; a++)
        #pragma unroll
        for (int b = 0; b < 8; b++) oa[a][b] = 0.f;
    for (int vb = 0; vb < 4; vb++) {
        __syncthreads();   // softmax done (vb=0) / prev compute done (vb>0)
        for (int idx = tid; idx < 4096; idx += 256)
            ((float4*)kv)[idx] = ((const float4*)&g_v[(base + vb*256)*DD])[idx];
        __syncthreads();
        for (int jj = 0; jj < 64; jj++) {
            int jl = (kg << 6) + jj;
            int j = vb*256 + jl;
            float p[4], vv[8];
            #pragma unroll
            for (int a = 0; a < 4; a++) p[a] = s[(i02 + a)*SS + j];
            #pragma unroll
            for (int b = 0; b < 8; b++) vv[b] = kv[jl*64 + dg + (b << 3)];
            #pragma unroll
            for (int a = 0; a < 4; a++)
                #pragma unroll
                for (int b = 0; b < 8; b++) oa[a][b] += p[a] * vv[b];
        }
    }
    __syncthreads();
    // k-split reduce via smem (reuse s)
    #pragma unroll
    for (int a = 0; a < 4; a++)
        #pragma unroll
        for (int b = 0; b < 8; b++)
            s[(kg*32 + i02 + a)*64 + dg + (b << 3)] = oa[a][b];
    __syncthreads();
    for (int idx = tid; idx < 2048; idx += 256) {
        int i = idx >> 6, d = idx & 63;
        float vsum = s[i*64 + d] + s[(32 + i)*64 + d]
                   + s[(64 + i)*64 + d] + s[(96 + i)*64 + d];
        // out layout (N, L, H, D) == (N, L, E)
        out[((n*LQ + q0 + i)*HH + h)*DD + d] = vsum;
    }
}

// ---------------------------------------------------------------------------
extern "C" void kernel_launch(void* const* d_in, const int* in_sizes, int n_in,
                              void* d_out, int out_size) {
    const float* x   = (const float*)d_in[0];
    const float* Wq  = (const float*)d_in[1];
    const float* Wk  = (const float*)d_in[2];
    const float* Wv  = (const float*)d_in[3];
    const float* Wfc = (const float*)d_in[4];

    float* out  = (float*)d_out;
    float* attn = out + (size_t)NB * LQ * EE;   // out first, then attn

    prep_kernel<<<1, 256>>>(Wv, Wfc);

    size_t proj_smem = (size_t)(4*64*65 + 64*64) * sizeof(float);   // 82944
    cudaFuncSetAttribute(proj_kernel,
                         cudaFuncAttributeMaxDynamicSharedMemorySize,
                         (int)proj_smem);
    proj_kernel<<<NB*HH*16, 256, proj_smem>>>(x, Wq, Wk);

    size_t attn_smem = (size_t)(32*SS + 64*33 + 16448) * sizeof(float); // 205440
    cudaFuncSetAttribute(attn_kernel,
                         cudaFuncAttributeMaxDynamicSharedMemorySize,
                         (int)attn_smem);
    attn_kernel<<<NB*HH*32, 256, attn_smem>>>(attn, out);
}

// round 2
// speedup vs baseline: 1.8514x; 1.8514x over previous
#include <cuda_runtime.h>
#include <math.h>
#include <stdint.h>

#define NB 8
#define LQ 1024
#define HH 16
#define DD 64
#define EE 1024
#define ROWS (NB*HH*LQ)   // 131072 head-rows

// Scratch (static device globals — no allocation)
__device__ float g_q[ROWS*DD];
__device__ float g_k[ROWS*DD];
__device__ float g_v[ROWS*DD];   // v' = x @ (Wv@Wfc)
__device__ float g_Wvf[DD*DD];

__device__ __forceinline__ float tf32r(float x) {
    uint32_t u;
    asm("cvt.rna.tf32.f32 %0, %1;" : "=r"(u) : "f"(x));
    return __uint_as_float(u);
}

__device__ __forceinline__ void mma_tf32(float d[4],
        uint32_t a0, uint32_t a1, uint32_t a2, uint32_t a3,
        uint32_t b0, uint32_t b1) {
    asm volatile(
        "mma.sync.aligned.m16n8k8.row.col.f32.tf32.tf32.f32 "
        "{%0,%1,%2,%3},{%4,%5,%6,%7},{%8,%9},{%0,%1,%2,%3};"
        : "+f"(d[0]), "+f"(d[1]), "+f"(d[2]), "+f"(d[3])
        : "r"(a0), "r"(a1), "r"(a2), "r"(a3), "r"(b0), "r"(b1));
}

// ---------------------------------------------------------------------------
// prep: Wvf = Wv @ Wfc  (64x64 @ 64x64)
// ---------------------------------------------------------------------------
__global__ void prep_kernel(const float* __restrict__ Wv,
                            const float* __restrict__ Wfc) {
    __shared__ float wv[64*64];
    __shared__ float wf[64*64];
    int tid = threadIdx.x;
    for (int i = tid; i < 4096; i += 256) { wv[i] = Wv[i]; wf[i] = Wfc[i]; }
    __syncthreads();
    for (int e = tid; e < 4096; e += 256) {
        int r = e >> 6, c = e & 63;
        float acc = 0.f;
        #pragma unroll 8
        for (int u = 0; u < 64; u++) acc += wv[r*64 + u] * wf[u*64 + c];
        g_Wvf[e] = acc;
    }
}

// ---------------------------------------------------------------------------
// projection: per (n, h, 64-row l-tile): q = x@(Wq*0.06/32), k = x@Wk, v' = x@Wvf
// ---------------------------------------------------------------------------
__global__ __launch_bounds__(256) void proj_kernel(const float* __restrict__ x,
                                                   const float* __restrict__ Wq,
                                                   const float* __restrict__ Wk) {
    extern __shared__ float sm[];
    float* xs = sm;               // 64*65
    float* ws = xs + 64*65;       // 3 * 64*65
    float* os = ws + 3*64*65;     // 64*64
    const int tid = threadIdx.x;
    const int bid = blockIdx.x;
    const int n = bid >> 8, h = (bid >> 4) & 15, lt = bid & 15;
    const int l0 = lt << 6;
    const float qs = 0.06f / 32.0f;

    for (int idx = tid; idx < 1024; idx += 256) {
        int l = idx >> 4, t4 = (idx & 15) << 2;
        float4 v = *(const float4*)&x[(n*LQ + l0 + l)*EE + (h << 6) + t4];
        float* p = &xs[l*65 + t4];
        p[0] = v.x; p[1] = v.y; p[2] = v.z; p[3] = v.w;
    }
    for (int idx = tid; idx < 4096; idx += 256) {
        int t = idx >> 6, d = idx & 63;
        ws[t*65 + d]            = Wq[idx] * qs;
        ws[64*65 + t*65 + d]    = Wk[idx];
        ws[2*64*65 + t*65 + d]  = g_Wvf[idx];
    }
    __syncthreads();

    const int tl = tid & 15, td = tid >> 4;
    float* gouts[3] = {g_q, g_k, g_v};
    for (int w = 0; w < 3; w++) {
        const float* W = ws + w*64*65;
        float acc[4][4] = {};
        for (int t = 0; t < 64; t++) {
            float xv[4], wv[4];
            #pragma unroll
            for (int a = 0; a < 4; a++) xv[a] = xs[(tl*4 + a)*65 + t];
            #pragma unroll
            for (int b = 0; b < 4; b++) wv[b] = W[t*65 + td*4 + b];
            #pragma unroll
            for (int a = 0; a < 4; a++)
                #pragma unroll
                for (int b = 0; b < 4; b++) acc[a][b] += xv[a] * wv[b];
        }
        #pragma unroll
        for (int a = 0; a < 4; a++)
            #pragma unroll
            for (int b = 0; b < 4; b++)
                os[(tl*4 + a)*64 + td*4 + b] = acc[a][b];
        __syncthreads();
        float* gp = gouts[w] + ((n*HH + h)*LQ + l0)*DD;
        for (int idx = tid; idx < 1024; idx += 256)
            ((float4*)gp)[idx] = ((const float4*)os)[idx];
        __syncthreads();
    }
}

// ---------------------------------------------------------------------------
// attention (tf32 mma): block = (n, h, 16-query tile). 256 threads = 8 warps.
//   S tile 16x1024 fp32 in smem (stride 1036, conflict-free mma frag loads)
//   phase 1: S = Q K^T  — 8 chunks of 128 keys; warp owns 16 key-cols/chunk
//   phase 2: softmax rows (warp per 2 rows), write normalized attn
//   phase 3: out = P V' — warp owns 16-key strip/chunk, 16x64 reg accum,
//            smem k-split reduce over 8 warps
// smem floats: 16*1036 + 128*68 + 16*68 = 26368  -> 105472 B  (2 blocks/SM)
// ---------------------------------------------------------------------------
#define SSTR 1036
#define KSTR 68
__global__ __launch_bounds__(256, 2) void attn_kernel(float* __restrict__ attn,
                                                      float* __restrict__ out) {
    extern __shared__ float sm[];
    float* S  = sm;                 // 16 x 1036
    float* KV = S + 16*SSTR;        // 128 x 68  (also reduce buffer 8 x 1088)
    float* Qs = KV + 128*KSTR;      // 16 x 68
    const int tid = threadIdx.x, w = tid >> 5, lane = tid & 31;
    const int bid = blockIdx.x;
    const int n = bid >> 10, h = (bid >> 6) & 15, qb = bid & 63;
    const int q0 = qb << 4;
    const int base = (n*HH + h)*LQ;
    const int m = lane >> 2, kq = lane & 3;   // groupID, threadInGroup

    // ---- load Q tile (16x64), tf32-rounded ----
    {
        int idx = tid;   // exactly 256 float4
        int r = idx >> 4, d4 = (idx & 15) << 2;
        float4 v = *(const float4*)&g_q[(base + q0 + r)*DD + d4];
        float* p = &Qs[r*KSTR + d4];
        p[0] = tf32r(v.x); p[1] = tf32r(v.y); p[2] = tf32r(v.z); p[3] = tf32r(v.w);
    }
    __syncthreads();

    // Q fragments held for all chunks: 8 k-steps x 4 regs
    uint32_t qf[8][4];
    #pragma unroll
    for (int kk = 0; kk < 8; kk++) {
        qf[kk][0] = __float_as_uint(Qs[m*KSTR       + kk*8 + kq]);
        qf[kk][1] = __float_as_uint(Qs[(m+8)*KSTR   + kk*8 + kq]);
        qf[kk][2] = __float_as_uint(Qs[m*KSTR       + kk*8 + kq + 4]);
        qf[kk][3] = __float_as_uint(Qs[(m+8)*KSTR   + kk*8 + kq + 4]);
    }

    // ---- phase 1: scores ----
    for (int c = 0; c < 8; c++) {
        __syncthreads();   // prev chunk consumed
        for (int idx = tid; idx < 2048; idx += 256) {
            int j = idx >> 4, d4 = (idx & 15) << 2;
            float4 v = *(const float4*)&g_k[(base + c*128 + j)*DD + d4];
            float* p = &KV[j*KSTR + d4];
            p[0] = tf32r(v.x); p[1] = tf32r(v.y); p[2] = tf32r(v.z); p[3] = tf32r(v.w);
        }
        __syncthreads();
        float acc[2][4] = {};
        #pragma unroll
        for (int kk = 0; kk < 8; kk++) {
            #pragma unroll
            for (int nt = 0; nt < 2; nt++) {
                int n0 = w*16 + nt*8;
                uint32_t b0 = __float_as_uint(KV[(n0 + m)*KSTR + kk*8 + kq]);
                uint32_t b1 = __float_as_uint(KV[(n0 + m)*KSTR + kk*8 + kq + 4]);
                mma_tf32(acc[nt], qf[kk][0], qf[kk][1], qf[kk][2], qf[kk][3], b0, b1);
            }
        }
        #pragma unroll
        for (int nt = 0; nt < 2; nt++) {
            int col = c*128 + w*16 + nt*8 + 2*kq;
            S[m*SSTR + col]         = acc[nt][0];
            S[m*SSTR + col + 1]     = acc[nt][1];
            S[(m+8)*SSTR + col]     = acc[nt][2];
            S[(m+8)*SSTR + col + 1] = acc[nt][3];
        }
    }
    __syncthreads();

    // ---- phase 2: softmax (warp w -> rows 2w, 2w+1) ----
    for (int rr = 0; rr < 2; rr++) {
        int row = w*2 + rr;
        float* srow = S + row*SSTR;
        float mx = -1e30f;
        for (int t = lane; t < 1024; t += 32) mx = fmaxf(mx, srow[t]);
        #pragma unroll
        for (int off = 16; off; off >>= 1)
            mx = fmaxf(mx, __shfl_xor_sync(0xffffffffu, mx, off));
        float sum = 0.f;
        for (int t = lane; t < 1024; t += 32) {
            float e = __expf(srow[t] - mx);
            srow[t] = e;
            sum += e;
        }
        #pragma unroll
        for (int off = 16; off; off >>= 1)
            sum += __shfl_xor_sync(0xffffffffu, sum, off);
        float inv = 1.0f / sum;
        float* arow = attn + (size_t)(base + q0 + row) * 1024;
        for (int t = lane; t < 1024; t += 32) {
            float vv = srow[t] * inv;
            srow[t] = vv;
            arow[t] = vv;
        }
    }

    // ---- phase 3: out = P @ V' ----
    float oacc[8][4] = {};
    for (int c = 0; c < 8; c++) {
        __syncthreads();   // softmax done (c=0) / prev V chunk consumed
        for (int idx = tid; idx < 2048; idx += 256) {
            int j = idx >> 4, d4 = (idx & 15) << 2;
            float4 v = *(const float4*)&g_v[(base + c*128 + j)*DD + d4];
            float* p = &KV[j*KSTR + d4];
            p[0] = tf32r(v.x); p[1] = tf32r(v.y); p[2] = tf32r(v.z); p[3] = tf32r(v.w);
        }
        __syncthreads();
        #pragma unroll
        for (int kk = 0; kk < 2; kk++) {
            int k0 = w*16 + kk*8;          // key offset within chunk
            int kg = c*128 + k0;           // global col in S
            uint32_t a0 = __float_as_uint(tf32r(S[m*SSTR     + kg + kq]));
            uint32_t a1 = __float_as_uint(tf32r(S[(m+8)*SSTR + kg + kq]));
            uint32_t a2 = __float_as_uint(tf32r(S[m*SSTR     + kg + kq + 4]));
            uint32_t a3 = __float_as_uint(tf32r(S[(m+8)*SSTR + kg + kq + 4]));
            #pragma unroll
            for (int nt = 0; nt < 8; nt++) {
                uint32_t b0 = __float_as_uint(KV[(k0 + kq)*KSTR     + nt*8 + m]);
                uint32_t b1 = __float_as_uint(KV[(k0 + kq + 4)*KSTR + nt*8 + m]);
                mma_tf32(oacc[nt], a0, a1, a2, a3, b0, b1);
            }
        }
    }
    __syncthreads();

    // k-split reduce across 8 warps via smem (reuse KV: 8 x 16 x 68)
    float* red = KV;
    #pragma unroll
    for (int nt = 0; nt < 8; nt++) {
        int col = nt*8 + 2*kq;
        red[w*1088 + m*68 + col]           = oacc[nt][0];
        red[w*1088 + m*68 + col + 1]       = oacc[nt][1];
        red[w*1088 + (m+8)*68 + col]       = oacc[nt][2];
        red[w*1088 + (m+8)*68 + col + 1]   = oacc[nt][3];
    }
    __syncthreads();
    for (int idx = tid; idx < 1024; idx += 256) {
        int i = idx >> 6, d = idx & 63;
        float s = 0.f;
        #pragma unroll
        for (int ww = 0; ww < 8; ww++) s += red[ww*1088 + i*68 + d];
        out[((n*LQ + q0 + i)*HH + h)*DD + d] = s;
    }
}

// ---------------------------------------------------------------------------
extern "C" void kernel_launch(void* const* d_in, const int* in_sizes, int n_in,
                              void* d_out, int out_size) {
    const float* x   = (const float*)d_in[0];
    const float* Wq  = (const float*)d_in[1];
    const float* Wk  = (const float*)d_in[2];
    const float* Wv  = (const float*)d_in[3];
    const float* Wfc = (const float*)d_in[4];

    float* out  = (float*)d_out;
    float* attn = out + (size_t)NB * LQ * EE;   // out first, then attn

    prep_kernel<<<1, 256>>>(Wv, Wfc);

    size_t proj_smem = (size_t)(4*64*65 + 64*64) * sizeof(float);   // 82944
    cudaFuncSetAttribute(proj_kernel,
                         cudaFuncAttributeMaxDynamicSharedMemorySize,
                         (int)proj_smem);
    proj_kernel<<<NB*HH*16, 256, proj_smem>>>(x, Wq, Wk);

    size_t attn_smem = (size_t)(16*SSTR + 128*KSTR + 16*KSTR) * sizeof(float); // 105472
    cudaFuncSetAttribute(attn_kernel,
                         cudaFuncAttributeMaxDynamicSharedMemorySize,
                         (int)attn_smem);
    attn_kernel<<<NB*HH*64, 256, attn_smem>>>(attn, out);
}

// round 3
// speedup vs baseline: 2.6558x; 1.4344x over previous
#include <cuda_runtime.h>
#include <cuda_fp16.h>
#include <math.h>
#include <stdint.h>

#define NB 8
#define LQ 1024
#define HH 16
#define DD 64
#define EE 1024
#define ROWS (NB*HH*LQ)   // 131072 head-rows

// Scratch (static device globals — no allocation)
__device__ __half g_q[ROWS*DD];
__device__ __half g_k[ROWS*DD];
__device__ __half g_v[ROWS*DD];   // v' = x @ (Wv@Wfc), stored TRANSPOSED: [n,h,d,l]
__device__ float  g_Wvf[DD*DD];

__device__ __forceinline__ void mma_f16(float d[4],
        uint32_t a0, uint32_t a1, uint32_t a2, uint32_t a3,
        uint32_t b0, uint32_t b1) {
    asm volatile(
        "mma.sync.aligned.m16n8k16.row.col.f32.f16.f16.f32 "
        "{%0,%1,%2,%3},{%4,%5,%6,%7},{%8,%9},{%0,%1,%2,%3};"
        : "+f"(d[0]), "+f"(d[1]), "+f"(d[2]), "+f"(d[3])
        : "r"(a0), "r"(a1), "r"(a2), "r"(a3), "r"(b0), "r"(b1));
}

// ---------------------------------------------------------------------------
// prep: Wvf = Wv @ Wfc  (64x64 @ 64x64), 1024 threads, 4 outputs each
// ---------------------------------------------------------------------------
__global__ __launch_bounds__(1024) void prep_kernel(const float* __restrict__ Wv,
                                                    const float* __restrict__ Wfc) {
    __shared__ float wv[64*64];
    __shared__ float wf[64*64];
    int tid = threadIdx.x;
    for (int i = tid; i < 4096; i += 1024) { wv[i] = Wv[i]; wf[i] = Wfc[i]; }
    __syncthreads();
    int r = tid >> 4, c4 = (tid & 15) << 2;
    float4 acc = {0.f, 0.f, 0.f, 0.f};
    #pragma unroll 8
    for (int u = 0; u < 64; u++) {
        float a = wv[r*64 + u];
        float4 b = *(const float4*)&wf[u*64 + c4];
        acc.x += a*b.x; acc.y += a*b.y; acc.z += a*b.z; acc.w += a*b.w;
    }
    *(float4*)&g_Wvf[r*64 + c4] = acc;
}

// ---------------------------------------------------------------------------
// projection: per (n, h, 64-row l-tile): q = x@(Wq*0.06/32), k = x@Wk, v' = x@Wvf
// outputs fp16; g_v written transposed ([d][l])
// ---------------------------------------------------------------------------
__global__ __launch_bounds__(256) void proj_kernel(const float* __restrict__ x,
                                                   const float* __restrict__ Wq,
                                                   const float* __restrict__ Wk) {
    extern __shared__ float sm[];
    float* xs = sm;               // 64*65
    float* ws = xs + 64*65;       // 3 * 64*65
    float* os = ws + 3*64*65;     // 64*64
    const int tid = threadIdx.x;
    const int bid = blockIdx.x;
    const int n = bid >> 8, h = (bid >> 4) & 15, lt = bid & 15;
    const int l0 = lt << 6;
    const float qs = 0.06f / 32.0f;

    for (int idx = tid; idx < 1024; idx += 256) {
        int l = idx >> 4, t4 = (idx & 15) << 2;
        float4 v = *(const float4*)&x[(n*LQ + l0 + l)*EE + (h << 6) + t4];
        float* p = &xs[l*65 + t4];
        p[0] = v.x; p[1] = v.y; p[2] = v.z; p[3] = v.w;
    }
    for (int idx = tid; idx < 4096; idx += 256) {
        int t = idx >> 6, d = idx & 63;
        ws[t*65 + d]            = Wq[idx] * qs;
        ws[64*65 + t*65 + d]    = Wk[idx];
        ws[2*64*65 + t*65 + d]  = g_Wvf[idx];
    }
    __syncthreads();

    const int tl = tid & 15, td = tid >> 4;
    for (int w = 0; w < 3; w++) {
        const float* W = ws + w*64*65;
        float acc[4][4] = {};
        for (int t = 0; t < 64; t++) {
            float xv[4], wv[4];
            #pragma unroll
            for (int a = 0; a < 4; a++) xv[a] = xs[(tl*4 + a)*65 + t];
            #pragma unroll
            for (int b = 0; b < 4; b++) wv[b] = W[t*65 + td*4 + b];
            #pragma unroll
            for (int a = 0; a < 4; a++)
                #pragma unroll
                for (int b = 0; b < 4; b++) acc[a][b] += xv[a] * wv[b];
        }
        if (w < 2) {
            #pragma unroll
            for (int a = 0; a < 4; a++)
                #pragma unroll
                for (int b = 0; b < 4; b++)
                    os[(tl*4 + a)*64 + td*4 + b] = acc[a][b];
        } else {
            // transposed store: os[d][l]
            #pragma unroll
            for (int a = 0; a < 4; a++)
                #pragma unroll
                for (int b = 0; b < 4; b++)
                    os[(td*4 + b)*64 + tl*4 + a] = acc[a][b];
        }
        __syncthreads();
        if (w < 2) {
            __half* gp = (w == 0 ? g_q : g_k) + ((n*HH + h)*LQ + l0)*DD;
            for (int idx = tid; idx < 2048; idx += 256) {
                int row = idx >> 5, d2 = (idx & 31) << 1;
                __half2 hv = __floats2half2_rn(os[row*64 + d2], os[row*64 + d2 + 1]);
                *(__half2*)(gp + row*64 + d2) = hv;
            }
        } else {
            __half* gp = g_v + ((n*HH + h)*DD)*LQ + l0;
            for (int idx = tid; idx < 2048; idx += 256) {
                int d = idx >> 5, l2 = (idx & 31) << 1;
                __half2 hv = __floats2half2_rn(os[d*64 + l2], os[d*64 + l2 + 1]);
                *(__half2*)(gp + d*LQ + l2) = hv;
            }
        }
        __syncthreads();
    }
}

// ---------------------------------------------------------------------------
// attention (fp16 mma m16n8k16): block = (n, h, 32-query tile). 512 thr, 16 warps.
// smem:
//   S   fp32 [32][1028]            131584 B  (raw scores -> softmax)
//   Ph  fp16 [32][1024] swizzled    65536 B  (normalized P for phase 3)
//   KV  fp16 16384 B  (K chunk [128 keys][64 d] / V^T chunk [64 d][128 keys], swizzled)
//   Qs  fp16 [32][64] swizzled       4096 B
// total 217600 B -> 1 block/SM, 16 warps
// ---------------------------------------------------------------------------
#define SSTR 1028
#define SMEM_S   0
#define SMEM_PH  131584
#define SMEM_KV  197120
#define SMEM_QS  213504
#define SMEM_TOT 217600

__global__ __launch_bounds__(512, 1) void attn_kernel(float* __restrict__ attn,
                                                      float* __restrict__ out) {
    extern __shared__ char smraw[];
    float*  S  = (float*)(smraw + SMEM_S);
    __half* Ph = (__half*)(smraw + SMEM_PH);
    __half* KV = (__half*)(smraw + SMEM_KV);
    __half* Qs = (__half*)(smraw + SMEM_QS);

    const int tid = threadIdx.x, w = tid >> 5, lane = tid & 31;
    const int bid = blockIdx.x;
    const int n = bid >> 9, h = (bid >> 5) & 15, qb = bid & 31;
    const int q0 = qb << 5;
    const int base = (n*HH + h)*LQ;
    const int g = lane >> 2, tg = lane & 3;
    const int wm = w & 1, wn = w >> 1;

    // ---- load Q tile (32x64 half), swizzled ----
    if (tid < 256) {
        int r = tid >> 3, c8 = tid & 7;
        const uint4* src = (const uint4*)(g_q + (base + q0 + r)*DD) + c8;
        *(uint4*)(Qs + r*64 + ((c8 ^ (r & 7)) << 3)) = *src;
    }
    __syncthreads();

    // Q fragments for 4 k-steps (rows wm*16+g, +8)
    uint32_t qf[4][4];
    {
        int r0 = wm*16 + g, r1 = r0 + 8;
        #pragma unroll
        for (int kk = 0; kk < 4; kk++) {
            int c8a = 2*kk, c8b = 2*kk + 1;
            qf[kk][0] = *(const uint32_t*)(Qs + r0*64 + ((c8a ^ g) << 3) + 2*tg);
            qf[kk][1] = *(const uint32_t*)(Qs + r1*64 + ((c8a ^ g) << 3) + 2*tg);
            qf[kk][2] = *(const uint32_t*)(Qs + r0*64 + ((c8b ^ g) << 3) + 2*tg);
            qf[kk][3] = *(const uint32_t*)(Qs + r1*64 + ((c8b ^ g) << 3) + 2*tg);
        }
    }

    // ---- phase 1: S = Q K^T, 8 chunks of 128 keys ----
    for (int c = 0; c < 8; c++) {
        __syncthreads();
        #pragma unroll
        for (int i = tid; i < 1024; i += 512) {
            int r = i >> 3, c8 = i & 7;
            const uint4* src = (const uint4*)(g_k + (base + c*128 + r)*DD) + c8;
            *(uint4*)(KV + r*64 + ((c8 ^ (r & 7)) << 3)) = *src;
        }
        __syncthreads();
        float acc[2][4] = {};
        #pragma unroll
        for (int kk = 0; kk < 4; kk++) {
            #pragma unroll
            for (int nt = 0; nt < 2; nt++) {
                int row = wn*16 + nt*8 + g;
                uint32_t b0 = *(const uint32_t*)(KV + row*64 + (((2*kk)   ^ g) << 3) + 2*tg);
                uint32_t b1 = *(const uint32_t*)(KV + row*64 + (((2*kk+1) ^ g) << 3) + 2*tg);
                mma_f16(acc[nt], qf[kk][0], qf[kk][1], qf[kk][2], qf[kk][3], b0, b1);
            }
        }
        int r0 = wm*16 + g;
        #pragma unroll
        for (int nt = 0; nt < 2; nt++) {
            int col = c*128 + wn*16 + nt*8 + 2*tg;
            *(float2*)&S[r0*SSTR + col]       = make_float2(acc[nt][0], acc[nt][1]);
            *(float2*)&S[(r0+8)*SSTR + col]   = make_float2(acc[nt][2], acc[nt][3]);
        }
    }
    __syncthreads();

    // ---- phase 2: softmax (warp w -> rows 2w, 2w+1); write attn + Ph(fp16) ----
    for (int rr = 0; rr < 2; rr++) {
        int row = w*2 + rr;
        float* srow = S + row*SSTR;
        float mx = -1e30f;
        for (int t = lane*4; t < 1024; t += 128) {
            float4 v = *(const float4*)(srow + t);
            mx = fmaxf(mx, fmaxf(fmaxf(v.x, v.y), fmaxf(v.z, v.w)));
        }
        #pragma unroll
        for (int off = 16; off; off >>= 1)
            mx = fmaxf(mx, __shfl_xor_sync(0xffffffffu, mx, off));
        float sum = 0.f;
        for (int t = lane*4; t < 1024; t += 128) {
            float4 v = *(const float4*)(srow + t);
            v.x = __expf(v.x - mx); v.y = __expf(v.y - mx);
            v.z = __expf(v.z - mx); v.w = __expf(v.w - mx);
            *(float4*)(srow + t) = v;
            sum += v.x + v.y + v.z + v.w;
        }
        #pragma unroll
        for (int off = 16; off; off >>= 1)
            sum += __shfl_xor_sync(0xffffffffu, sum, off);
        float inv = 1.0f / sum;
        float* arow = attn + (size_t)(base + q0 + row) * 1024;
        for (int t = lane*4; t < 1024; t += 128) {
            float4 v = *(const float4*)(srow + t);
            v.x *= inv; v.y *= inv; v.z *= inv; v.w *= inv;
            *(float4*)(arow + t) = v;
            int c8 = t >> 3;
            __half* pp = Ph + row*1024 + ((c8 ^ (row & 7)) << 3) + (t & 7);
            __half2 h0 = __floats2half2_rn(v.x, v.y);
            __half2 h1 = __floats2half2_rn(v.z, v.w);
            *(uint2*)pp = make_uint2(*(uint32_t*)&h0, *(uint32_t*)&h1);
        }
    }

    // ---- phase 3: out = P V' (warp owns 16 queries x 8 dims, full k) ----
    float oacc[4] = {0.f, 0.f, 0.f, 0.f};
    const int r0 = wm*16 + g, r1 = r0 + 8;
    const int nrow = wn*8 + g;   // V^T row (dim index) for B frags
    for (int c = 0; c < 8; c++) {
        __syncthreads();
        #pragma unroll
        for (int i = tid; i < 1024; i += 512) {
            int r = i >> 4, c8 = i & 15;
            const uint4* src = (const uint4*)(g_v + ((n*HH + h)*DD + r)*LQ + c*128) + c8;
            *(uint4*)(KV + r*128 + ((c8 ^ (r & 7)) << 3)) = *src;
        }
        __syncthreads();
        #pragma unroll
        for (int ks = 0; ks < 8; ks++) {
            int c8a = c*16 + 2*ks, c8b = c8a + 1;
            uint32_t a0 = *(const uint32_t*)(Ph + r0*1024 + ((c8a ^ g) << 3) + 2*tg);
            uint32_t a1 = *(const uint32_t*)(Ph + r1*1024 + ((c8a ^ g) << 3) + 2*tg);
            uint32_t a2 = *(const uint32_t*)(Ph + r0*1024 + ((c8b ^ g) << 3) + 2*tg);
            uint32_t a3 = *(const uint32_t*)(Ph + r1*1024 + ((c8b ^ g) << 3) + 2*tg);
            uint32_t b0 = *(const uint32_t*)(KV + nrow*128 + (((2*ks)   ^ g) << 3) + 2*tg);
            uint32_t b1 = *(const uint32_t*)(KV + nrow*128 + (((2*ks+1) ^ g) << 3) + 2*tg);
            mma_f16(oacc, a0, a1, a2, a3, b0, b1);
        }
    }
    // direct write (no k-split reduce): warp tile O[16][8]
    {
        int dcol = wn*8 + 2*tg;
        float* o0 = out + ((size_t)(n*LQ + q0 + r0)*HH + h)*DD + dcol;
        float* o1 = out + ((size_t)(n*LQ + q0 + r0 + 8)*HH + h)*DD + dcol;
        *(float2*)o0 = make_float2(oacc[0], oacc[1]);
        *(float2*)o1 = make_float2(oacc[2], oacc[3]);
    }
}

// ---------------------------------------------------------------------------
extern "C" void kernel_launch(void* const* d_in, const int* in_sizes, int n_in,
                              void* d_out, int out_size) {
    const float* x   = (const float*)d_in[0];
    const float* Wq  = (const float*)d_in[1];
    const float* Wk  = (const float*)d_in[2];
    const float* Wv  = (const float*)d_in[3];
    const float* Wfc = (const float*)d_in[4];

    float* out  = (float*)d_out;
    float* attn = out + (size_t)NB * LQ * EE;   // out first, then attn

    prep_kernel<<<1, 1024>>>(Wv, Wfc);

    size_t proj_smem = (size_t)(4*64*65 + 64*64) * sizeof(float);   // 82944
    cudaFuncSetAttribute(proj_kernel,
                         cudaFuncAttributeMaxDynamicSharedMemorySize,
                         (int)proj_smem);
    proj_kernel<<<NB*HH*16, 256, proj_smem>>>(x, Wq, Wk);

    cudaFuncSetAttribute(attn_kernel,
                         cudaFuncAttributeMaxDynamicSharedMemorySize,
                         SMEM_TOT);
    attn_kernel<<<NB*HH*32, 512, SMEM_TOT>>>(attn, out);
}

// round 4
// speedup vs baseline: 3.4457x; 1.2975x over previous
#include <cuda_runtime.h>
#include <cuda_fp16.h>
#include <math.h>
#include <stdint.h>

#define NB 8
#define LQ 1024
#define HH 16
#define DD 64
#define EE 1024
#define ROWS (NB*HH*LQ)   // 131072 head-rows

// Scratch (static device globals — no allocation)
__device__ __half g_q[ROWS*DD];
__device__ __half g_k[ROWS*DD];
__device__ __half g_v[ROWS*DD];   // v' = x @ (Wv@Wfc), stored TRANSPOSED: [n,h,d,l]
__device__ float  g_Wvf[DD*DD];

__device__ __forceinline__ void mma_f16(float d[4],
        uint32_t a0, uint32_t a1, uint32_t a2, uint32_t a3,
        uint32_t b0, uint32_t b1) {
    asm volatile(
        "mma.sync.aligned.m16n8k16.row.col.f32.f16.f16.f32 "
        "{%0,%1,%2,%3},{%4,%5,%6,%7},{%8,%9},{%0,%1,%2,%3};"
        : "+f"(d[0]), "+f"(d[1]), "+f"(d[2]), "+f"(d[3])
        : "r"(a0), "r"(a1), "r"(a2), "r"(a3), "r"(b0), "r"(b1));
}

#define CP_ASYNC16(dst_u32, src_ptr) \
    asm volatile("cp.async.cg.shared.global [%0], [%1], 16;" :: "r"(dst_u32), "l"(src_ptr))
#define CP_COMMIT() asm volatile("cp.async.commit_group;" ::: "memory")
#define CP_WAIT(N)  asm volatile("cp.async.wait_group %0;" :: "n"(N) : "memory")

// ---------------------------------------------------------------------------
// prep: Wvf = Wv @ Wfc  (64x64 @ 64x64)
// ---------------------------------------------------------------------------
__global__ __launch_bounds__(1024) void prep_kernel(const float* __restrict__ Wv,
                                                    const float* __restrict__ Wfc) {
    __shared__ float wv[64*64];
    __shared__ float wf[64*64];
    int tid = threadIdx.x;
    for (int i = tid; i < 4096; i += 1024) { wv[i] = Wv[i]; wf[i] = Wfc[i]; }
    __syncthreads();
    int r = tid >> 4, c4 = (tid & 15) << 2;
    float4 acc = {0.f, 0.f, 0.f, 0.f};
    #pragma unroll 8
    for (int u = 0; u < 64; u++) {
        float a = wv[r*64 + u];
        float4 b = *(const float4*)&wf[u*64 + c4];
        acc.x += a*b.x; acc.y += a*b.y; acc.z += a*b.z; acc.w += a*b.w;
    }
    *(float4*)&g_Wvf[r*64 + c4] = acc;
}

// ---------------------------------------------------------------------------
// projection: per (n, h, 64-row l-tile): q = x@(Wq*0.06/32), k = x@Wk, v' = x@Wvf
// outputs fp16; g_v written transposed ([d][l])
// ---------------------------------------------------------------------------
__global__ __launch_bounds__(256) void proj_kernel(const float* __restrict__ x,
                                                   const float* __restrict__ Wq,
                                                   const float* __restrict__ Wk) {
    extern __shared__ float sm[];
    float* xs = sm;               // 64*65
    float* ws = xs + 64*65;       // 3 * 64*65
    float* os = ws + 3*64*65;     // 64*64
    const int tid = threadIdx.x;
    const int bid = blockIdx.x;
    const int n = bid >> 8, h = (bid >> 4) & 15, lt = bid & 15;
    const int l0 = lt << 6;
    const float qs = 0.06f / 32.0f;

    for (int idx = tid; idx < 1024; idx += 256) {
        int l = idx >> 4, t4 = (idx & 15) << 2;
        float4 v = *(const float4*)&x[(n*LQ + l0 + l)*EE + (h << 6) + t4];
        float* p = &xs[l*65 + t4];
        p[0] = v.x; p[1] = v.y; p[2] = v.z; p[3] = v.w;
    }
    for (int idx = tid; idx < 4096; idx += 256) {
        int t = idx >> 6, d = idx & 63;
        ws[t*65 + d]            = Wq[idx] * qs;
        ws[64*65 + t*65 + d]    = Wk[idx];
        ws[2*64*65 + t*65 + d]  = g_Wvf[idx];
    }
    __syncthreads();

    const int tl = tid & 15, td = tid >> 4;
    for (int w = 0; w < 3; w++) {
        const float* W = ws + w*64*65;
        float acc[4][4] = {};
        for (int t = 0; t < 64; t++) {
            float xv[4], wv[4];
            #pragma unroll
            for (int a = 0; a < 4; a++) xv[a] = xs[(tl*4 + a)*65 + t];
            #pragma unroll
            for (int b = 0; b < 4; b++) wv[b] = W[t*65 + td*4 + b];
            #pragma unroll
            for (int a = 0; a < 4; a++)
                #pragma unroll
                for (int b = 0; b < 4; b++) acc[a][b] += xv[a] * wv[b];
        }
        if (w < 2) {
            #pragma unroll
            for (int a = 0; a < 4; a++)
                #pragma unroll
                for (int b = 0; b < 4; b++)
                    os[(tl*4 + a)*64 + td*4 + b] = acc[a][b];
        } else {
            #pragma unroll
            for (int a = 0; a < 4; a++)
                #pragma unroll
                for (int b = 0; b < 4; b++)
                    os[(td*4 + b)*64 + tl*4 + a] = acc[a][b];
        }
        __syncthreads();
        if (w < 2) {
            __half* gp = (w == 0 ? g_q : g_k) + ((n*HH + h)*LQ + l0)*DD;
            for (int idx = tid; idx < 2048; idx += 256) {
                int row = idx >> 5, d2 = (idx & 31) << 1;
                __half2 hv = __floats2half2_rn(os[row*64 + d2], os[row*64 + d2 + 1]);
                *(__half2*)(gp + row*64 + d2) = hv;
            }
        } else {
            __half* gp = g_v + ((n*HH + h)*DD)*LQ + l0;
            for (int idx = tid; idx < 2048; idx += 256) {
                int d = idx >> 5, l2 = (idx & 31) << 1;
                __half2 hv = __floats2half2_rn(os[d*64 + l2], os[d*64 + l2 + 1]);
                *(__half2*)(gp + d*LQ + l2) = hv;
            }
        }
        __syncthreads();
    }
}

// ---------------------------------------------------------------------------
// attention v3: 32-query block, 512 threads, 16 warps, scores in registers.
//   warp (wm=w&1, wn=w>>1): rows wm*16+[0,16), cols wn*16+nt*8 within chunk
//   phase1: 8 K chunks (cp.async double buffered), acc[16][4] registers
//   softmax: quad shfl + 32x8 smem partial reduce; P -> swizzled fp16 Ph
//   attn pass: coalesced float4 writes from Ph
//   phase3: 8 V^T chunks (cp.async double buffered), Ph A-frags, direct out
// smem: Ph 64K | Kbuf 2x16K | Vbuf 2x16K | Qs 4K | redM 1K | redS 1K = 134K
// ---------------------------------------------------------------------------
#define SMEM_PH   0
#define SMEM_KB   65536
#define SMEM_VB   98304
#define SMEM_QS   131072
#define SMEM_REDM 135168
#define SMEM_REDS 136192
#define SMEM_TOT  137216

__global__ __launch_bounds__(512, 1) void attn_kernel(float* __restrict__ attn,
                                                      float* __restrict__ out) {
    extern __shared__ char smraw[];
    __half* Ph   = (__half*)(smraw + SMEM_PH);
    __half* Qs   = (__half*)(smraw + SMEM_QS);
    float*  redM = (float*)(smraw + SMEM_REDM);
    float*  redS = (float*)(smraw + SMEM_REDS);
    const uint32_t sbase = (uint32_t)__cvta_generic_to_shared(smraw);

    const int tid = threadIdx.x, w = tid >> 5, lane = tid & 31;
    const int bid = blockIdx.x;
    const int n = bid >> 9, h = (bid >> 5) & 15, qb = bid & 31;
    const int q0 = qb << 5;
    const int base = (n*HH + h)*LQ;
    const int g = lane >> 2, tg = lane & 3;
    const int wm = w & 1, wn = w >> 1;
    const int r0 = wm*16 + g, r1 = r0 + 8;

    const __half* kg0 = g_k + (size_t)base * DD;
    const __half* vg0 = g_v + (size_t)(n*HH + h) * DD * LQ;

    // issue K chunk 0
    {
        #pragma unroll
        for (int t = tid; t < 1024; t += 512) {
            int r = t >> 3, c8 = t & 7;
            CP_ASYNC16(sbase + SMEM_KB + (r*64 + ((c8 ^ (r & 7)) << 3))*2,
                       kg0 + r*64 + c8*8);
        }
        CP_COMMIT();
    }

    // load Q tile (32x64 half), swizzled
    if (tid < 256) {
        int r = tid >> 3, c8 = tid & 7;
        const uint4* src = (const uint4*)(g_q + (size_t)(base + q0 + r)*DD) + c8;
        *(uint4*)(Qs + r*64 + ((c8 ^ (r & 7)) << 3)) = *src;
    }
    __syncthreads();

    uint32_t qf[4][4];
    #pragma unroll
    for (int kk = 0; kk < 4; kk++) {
        int c8a = 2*kk, c8b = 2*kk + 1;
        qf[kk][0] = *(const uint32_t*)(Qs + r0*64 + ((c8a ^ g) << 3) + 2*tg);
        qf[kk][1] = *(const uint32_t*)(Qs + r1*64 + ((c8a ^ g) << 3) + 2*tg);
        qf[kk][2] = *(const uint32_t*)(Qs + r0*64 + ((c8b ^ g) << 3) + 2*tg);
        qf[kk][3] = *(const uint32_t*)(Qs + r1*64 + ((c8b ^ g) << 3) + 2*tg);
    }

    // ---- phase 1: scores into registers ----
    float acc[16][4];
    #pragma unroll
    for (int i = 0; i < 16; i++)
        #pragma unroll
        for (int j = 0; j < 4; j++) acc[i][j] = 0.f;

    #pragma unroll
    for (int c = 0; c < 8; c++) {
        CP_WAIT(0);
        __syncthreads();
        if (c < 7) {          // prefetch next K chunk
            const __half* kc = kg0 + (size_t)(c + 1)*128*DD;
            #pragma unroll
            for (int t = tid; t < 1024; t += 512) {
                int r = t >> 3, c8 = t & 7;
                CP_ASYNC16(sbase + SMEM_KB + ((c + 1) & 1)*16384
                           + (r*64 + ((c8 ^ (r & 7)) << 3))*2,
                           kc + r*64 + c8*8);
            }
            CP_COMMIT();
        } else {              // prefetch V chunk 0
            #pragma unroll
            for (int t = tid; t < 1024; t += 512) {
                int r = t >> 4, c8 = t & 15;
                CP_ASYNC16(sbase + SMEM_VB + (r*128 + ((c8 ^ (r & 7)) << 3))*2,
                           vg0 + r*LQ + c8*8);
            }
            CP_COMMIT();
        }
        const __half* Kc = (const __half*)(smraw + SMEM_KB + (c & 1)*16384);
        #pragma unroll
        for (int kk = 0; kk < 4; kk++) {
            #pragma unroll
            for (int nt = 0; nt < 2; nt++) {
                int row = wn*16 + nt*8 + g;
                uint32_t b0 = *(const uint32_t*)(Kc + row*64 + (((2*kk)   ^ g) << 3) + 2*tg);
                uint32_t b1 = *(const uint32_t*)(Kc + row*64 + (((2*kk+1) ^ g) << 3) + 2*tg);
                mma_f16(acc[c*2 + nt], qf[kk][0], qf[kk][1], qf[kk][2], qf[kk][3], b0, b1);
            }
        }
    }
    // issue V chunk 1 (fresh buffer)
    {
        #pragma unroll
        for (int t = tid; t < 1024; t += 512) {
            int r = t >> 4, c8 = t & 15;
            CP_ASYNC16(sbase + SMEM_VB + 16384 + (r*128 + ((c8 ^ (r & 7)) << 3))*2,
                       vg0 + r*LQ + 128 + c8*8);
        }
        CP_COMMIT();
    }

    // ---- phase 2: softmax (registers + small smem reduce) ----
    float m0 = -1e30f, m1 = -1e30f;
    #pragma unroll
    for (int i = 0; i < 16; i++) {
        m0 = fmaxf(m0, fmaxf(acc[i][0], acc[i][1]));
        m1 = fmaxf(m1, fmaxf(acc[i][2], acc[i][3]));
    }
    m0 = fmaxf(m0, __shfl_xor_sync(0xffffffffu, m0, 1));
    m0 = fmaxf(m0, __shfl_xor_sync(0xffffffffu, m0, 2));
    m1 = fmaxf(m1, __shfl_xor_sync(0xffffffffu, m1, 1));
    m1 = fmaxf(m1, __shfl_xor_sync(0xffffffffu, m1, 2));
    if (tg == 0) { redM[r0*8 + wn] = m0; redM[r1*8 + wn] = m1; }
    __syncthreads();
    m0 = -1e30f; m1 = -1e30f;
    #pragma unroll
    for (int k = 0; k < 8; k++) {
        m0 = fmaxf(m0, redM[r0*8 + k]);
        m1 = fmaxf(m1, redM[r1*8 + k]);
    }
    float s0 = 0.f, s1 = 0.f;
    #pragma unroll
    for (int i = 0; i < 16; i++) {
        acc[i][0] = __expf(acc[i][0] - m0); s0 += acc[i][0];
        acc[i][1] = __expf(acc[i][1] - m0); s0 += acc[i][1];
        acc[i][2] = __expf(acc[i][2] - m1); s1 += acc[i][2];
        acc[i][3] = __expf(acc[i][3] - m1); s1 += acc[i][3];
    }
    s0 += __shfl_xor_sync(0xffffffffu, s0, 1);
    s0 += __shfl_xor_sync(0xffffffffu, s0, 2);
    s1 += __shfl_xor_sync(0xffffffffu, s1, 1);
    s1 += __shfl_xor_sync(0xffffffffu, s1, 2);
    if (tg == 0) { redS[r0*8 + wn] = s0; redS[r1*8 + wn] = s1; }
    __syncthreads();
    s0 = 0.f; s1 = 0.f;
    #pragma unroll
    for (int k = 0; k < 8; k++) { s0 += redS[r0*8 + k]; s1 += redS[r1*8 + k]; }
    const float inv0 = 1.0f / s0, inv1 = 1.0f / s1;

    // write normalized P (fp16) to swizzled Ph
    #pragma unroll
    for (int c = 0; c < 8; c++) {
        #pragma unroll
        for (int nt = 0; nt < 2; nt++) {
            int i = c*2 + nt;
            int c8 = c*16 + wn*2 + nt;
            __half2 h0 = __floats2half2_rn(acc[i][0]*inv0, acc[i][1]*inv0);
            __half2 h1 = __floats2half2_rn(acc[i][2]*inv1, acc[i][3]*inv1);
            *(uint32_t*)(Ph + r0*1024 + ((c8 ^ g) << 3) + 2*tg) = *(uint32_t*)&h0;
            *(uint32_t*)(Ph + r1*1024 + ((c8 ^ g) << 3) + 2*tg) = *(uint32_t*)&h1;
        }
    }
    __syncthreads();

    // ---- attn pass: coalesced float4 writes from Ph ----
    {
        int r = tid >> 4, c16 = tid & 15;
        float* arow = attn + (size_t)(base + q0 + r) * 1024;
        int rsw = r & 7;
        #pragma unroll
        for (int j = 0; j < 16; j++) {
            int col4 = 4*c16 + 64*j;
            int c8 = col4 >> 3, off = col4 & 7;
            uint2 u = *(const uint2*)(Ph + r*1024 + ((c8 ^ rsw) << 3) + off);
            float2 fa = __half22float2(*(__half2*)&u.x);
            float2 fb = __half22float2(*(__half2*)&u.y);
            float4 o = make_float4(fa.x, fa.y, fb.x, fb.y);
            *(float4*)(arow + col4) = o;
        }
    }

    // ---- phase 3: out = P @ V' ----
    float oacc[4] = {0.f, 0.f, 0.f, 0.f};
    const int nrow = wn*8 + g;
    #pragma unroll
    for (int c = 0; c < 8; c++) {
        CP_WAIT(1);
        if (c == 7) { CP_WAIT(0); }
        __syncthreads();
        const __half* Vc = (const __half*)(smraw + SMEM_VB + (c & 1)*16384);
        #pragma unroll
        for (int ks = 0; ks < 8; ks++) {
            int c8a = c*16 + 2*ks, c8b = c8a + 1;
            uint32_t a0 = *(const uint32_t*)(Ph + r0*1024 + ((c8a ^ g) << 3) + 2*tg);
            uint32_t a1 = *(const uint32_t*)(Ph + r1*1024 + ((c8a ^ g) << 3) + 2*tg);
            uint32_t a2 = *(const uint32_t*)(Ph + r0*1024 + ((c8b ^ g) << 3) + 2*tg);
            uint32_t a3 = *(const uint32_t*)(Ph + r1*1024 + ((c8b ^ g) << 3) + 2*tg);
            uint32_t b0 = *(const uint32_t*)(Vc + nrow*128 + (((2*ks)   ^ g) << 3) + 2*tg);
            uint32_t b1 = *(const uint32_t*)(Vc + nrow*128 + (((2*ks+1) ^ g) << 3) + 2*tg);
            mma_f16(oacc, a0, a1, a2, a3, b0, b1);
        }
        __syncthreads();
        if (c + 2 < 8) {   // prefetch V chunk c+2 into buffer (c&1)
            const __half* vc = vg0 + (size_t)(c + 2)*128;
            #pragma unroll
            for (int t = tid; t < 1024; t += 512) {
                int r = t >> 4, c8 = t & 15;
                CP_ASYNC16(sbase + SMEM_VB + (c & 1)*16384
                           + (r*128 + ((c8 ^ (r & 7)) << 3))*2,
                           vc + r*LQ + c8*8);
            }
            CP_COMMIT();
        }
    }
    {
        int dcol = wn*8 + 2*tg;
        float* o0 = out + ((size_t)(n*LQ + q0 + r0)*HH + h)*DD + dcol;
        float* o1 = out + ((size_t)(n*LQ + q0 + r1)*HH + h)*DD + dcol;
        *(float2*)o0 = make_float2(oacc[0], oacc[1]);
        *(float2*)o1 = make_float2(oacc[2], oacc[3]);
    }
}

// ---------------------------------------------------------------------------
extern "C" void kernel_launch(void* const* d_in, const int* in_sizes, int n_in,
                              void* d_out, int out_size) {
    const float* x   = (const float*)d_in[0];
    const float* Wq  = (const float*)d_in[1];
    const float* Wk  = (const float*)d_in[2];
    const float* Wv  = (const float*)d_in[3];
    const float* Wfc = (const float*)d_in[4];

    float* out  = (float*)d_out;
    float* attn = out + (size_t)NB * LQ * EE;   // out first, then attn

    prep_kernel<<<1, 1024>>>(Wv, Wfc);

    size_t proj_smem = (size_t)(4*64*65 + 64*64) * sizeof(float);   // 82944
    cudaFuncSetAttribute(proj_kernel,
                         cudaFuncAttributeMaxDynamicSharedMemorySize,
                         (int)proj_smem);
    proj_kernel<<<NB*HH*16, 256, proj_smem>>>(x, Wq, Wk);

    cudaFuncSetAttribute(attn_kernel,
                         cudaFuncAttributeMaxDynamicSharedMemorySize,
                         SMEM_TOT);
    attn_kernel<<<NB*HH*32, 512, SMEM_TOT>>>(attn, out);
}